// round 13
// baseline (speedup 1.0000x reference)
#include <cuda_runtime.h>
#include <cuda_fp16.h>
#include <stdint.h>
#include <math.h>

#define BDIM   4
#define SDIM   2048
#define DDIM   4096
#define ODIM   4096
#define EDIM   8
#define RDIM   8
#define MDIM   (BDIM*SDIM)     // 8192
#define ERDIM  64
#define SCALING 2.0f

// ---------------- scratch (static device globals; no allocations) -------
__device__ __half g_xh[(size_t)MDIM * DDIM];     // 64 MB  x fp16
__device__ __half g_wh[(size_t)ODIM * DDIM];     // 32 MB  W fp16
__device__ __half g_lah[(size_t)ERDIM * DDIM];   // 512 KB lora_A fp16
__device__ float g_hp[2][MDIM * ERDIM];          // 4 MB   h k-split partials
__device__ float g_xpart[16][BDIM * DDIM];       // 1 MB   colsum partials
__device__ float g_xsum[BDIM * DDIM];
__device__ float g_w[BDIM * EDIM];

// ---------------- helpers ----------------
__device__ __forceinline__ uint32_t cvta_smem(const void* p) {
    return (uint32_t)__cvta_generic_to_shared(p);
}
__device__ __forceinline__ void cp16(uint32_t dst, const void* src) {
    asm volatile("cp.async.cg.shared.global [%0], [%1], 16;"
                 :: "r"(dst), "l"(src) : "memory");
}
__device__ __forceinline__ void cp_commit() {
    asm volatile("cp.async.commit_group;" ::: "memory");
}
__device__ __forceinline__ void cp_wait0() {
    asm volatile("cp.async.wait_group 0;" ::: "memory");
}
__device__ __forceinline__ void cp_wait1() {
    asm volatile("cp.async.wait_group 1;" ::: "memory");
}
__device__ __forceinline__ void ldsm4(uint32_t a, uint32_t* r) {
    asm volatile("ldmatrix.sync.aligned.m8n8.x4.shared.b16 {%0,%1,%2,%3}, [%4];"
                 : "=r"(r[0]), "=r"(r[1]), "=r"(r[2]), "=r"(r[3]) : "r"(a));
}
__device__ __forceinline__ void mma_f16(float* d, const uint32_t* a,
                                        uint32_t b0, uint32_t b1) {
    asm volatile(
        "mma.sync.aligned.m16n8k16.row.col.f32.f16.f16.f32 "
        "{%0,%1,%2,%3}, {%4,%5,%6,%7}, {%8,%9}, {%0,%1,%2,%3};"
        : "+f"(d[0]), "+f"(d[1]), "+f"(d[2]), "+f"(d[3])
        : "r"(a[0]), "r"(a[1]), "r"(a[2]), "r"(a[3]), "r"(b0), "r"(b1));
}
__device__ __forceinline__ uint2 pack_h4(float4 v) {
    __half2 a = __floats2half2_rn(v.x, v.y);
    __half2 b = __floats2half2_rn(v.z, v.w);
    uint2 u;
    u.x = *reinterpret_cast<uint32_t*>(&a);
    u.y = *reinterpret_cast<uint32_t*>(&b);
    return u;
}

// ================= kernel 1: fused conversions =================
__global__ void convall_kernel(const float* __restrict__ x,
                               const float* __restrict__ W,
                               const float* __restrict__ lA) {
    if (blockIdx.z < 4) {
        int b = blockIdx.z;
        int d = blockIdx.x * 256 + threadIdx.x;
        int ss = blockIdx.y;
        size_t base = ((size_t)(b * SDIM + ss * 128)) * DDIM + d;
        float acc = 0.0f;
#pragma unroll 4
        for (int s = 0; s < 128; ++s) {
            size_t idx = base + (size_t)s * DDIM;
            float v = x[idx];
            g_xh[idx] = __float2half_rn(v);
            acc += v;
        }
        g_xpart[ss][b * DDIM + d] = acc;
    } else if (blockIdx.z < 8) {
        int zq = blockIdx.z - 4;
        int t = (blockIdx.y * 16 + blockIdx.x) * 256 + threadIdx.x;
#pragma unroll 4
        for (int i = 0; i < 16; ++i) {
            size_t j = (((size_t)zq * 16 + i) * 65536 + t) * 4;
            float4 v = *(const float4*)(W + j);
            *(uint2*)(g_wh + j) = pack_h4(v);
        }
    } else {
        int t = (blockIdx.y * 16 + blockIdx.x) * 256 + threadIdx.x;
        size_t j = (size_t)t * 4;
        float4 v = *(const float4*)(lA + j);
        *(uint2*)(g_lah + j) = pack_h4(v);
    }
}

// ================= kernel 2: router (reduce partials + softmax) =========
__global__ void router_kernel(const float* __restrict__ rW,
                              const float* __restrict__ rb) {
    __shared__ float logits[BDIM][EDIM];
    for (int i = threadIdx.x; i < BDIM * DDIM; i += 1024) {
        float s = 0.0f;
#pragma unroll
        for (int p = 0; p < 16; ++p) s += g_xpart[p][i];
        g_xsum[i] = s;
    }
    __syncthreads();
    int w = threadIdx.x >> 5;
    int lane = threadIdx.x & 31;
    int b = w >> 3, e = w & 7;
    const float* xs = g_xsum + b * DDIM;
    const float* wr = rW + e * DDIM;
    float acc = 0.0f;
    for (int d = lane; d < DDIM; d += 32) acc += xs[d] * wr[d];
#pragma unroll
    for (int o = 16; o; o >>= 1) acc += __shfl_down_sync(0xffffffffu, acc, o);
    if (lane == 0) logits[b][e] = acc / (float)SDIM + rb[e];
    __syncthreads();
    if (threadIdx.x < BDIM) {
        int bb = threadIdx.x;
        float mx = -1e30f;
#pragma unroll
        for (int ee = 0; ee < EDIM; ++ee) mx = fmaxf(mx, logits[bb][ee]);
        float sum = 0.0f;
        float ex[EDIM];
#pragma unroll
        for (int ee = 0; ee < EDIM; ++ee) { ex[ee] = expf(logits[bb][ee] - mx); sum += ex[ee]; }
        float inv = SCALING / sum;
#pragma unroll
        for (int ee = 0; ee < EDIM; ++ee) g_w[bb * EDIM + ee] = ex[ee] * inv;
    }
}

// ================= kernel 3: h via HMMA (M=8192, N=64, k-split x2) ======
#define HB_OFF 16384
#define HBUF 24576
#define H_SMEM (3 * HBUF)
#define NT_H 32

__global__ void __launch_bounds__(256, 2) h_mma_kernel() {
    extern __shared__ __align__(128) char sm[];
    const int tid = threadIdx.x;
    const int lane = tid & 31, wid = tid >> 5;
    const int wm = wid & 3, wn = wid >> 2;
    const uint32_t sbase = cvta_smem(sm);
    const int m0 = blockIdx.x * 128;
    const int kb = blockIdx.y;
    const int kbase = kb * 2048;

    const int row16 = ((lane >> 3) & 1) * 8 + (lane & 7);
    const int khalf = lane >> 4;
    int arow[2], brow[2];
#pragma unroll
    for (int f = 0; f < 2; ++f) {
        arow[f] = wm * 32 + f * 16 + row16;
        brow[f] = wn * 32 + f * 16 + row16;
    }

    float acc[2][4][4];
#pragma unroll
    for (int i = 0; i < 2; ++i)
#pragma unroll
        for (int j = 0; j < 4; ++j)
#pragma unroll
            for (int k = 0; k < 4; ++k) acc[i][j][k] = 0.0f;

#define HSTAGE(bufofs, t)                                                    \
    do {                                                                     \
        _Pragma("unroll")                                                    \
        for (int i = 0; i < 4; ++i) {                                        \
            int idx = i * 256 + tid;                                         \
            int r = idx >> 3, seg = idx & 7;                                 \
            const __half* src = g_xh                                         \
                + (size_t)(m0 + r) * DDIM + kbase + (t) * 64 + seg * 8;      \
            cp16(sbase + (bufofs) + r * 128 + ((seg ^ (r & 7)) << 4), src);  \
        }                                                                    \
        _Pragma("unroll")                                                    \
        for (int i = 0; i < 2; ++i) {                                        \
            int idx = i * 256 + tid;                                         \
            int r = idx >> 3, seg = idx & 7;                                 \
            const __half* src = g_lah                                        \
                + (size_t)r * DDIM + kbase + (t) * 64 + seg * 8;             \
            cp16(sbase + (bufofs) + HB_OFF + r * 128                         \
                 + ((seg ^ (r & 7)) << 4), src);                             \
        }                                                                    \
    } while (0)

    HSTAGE(0, 0);
    cp_commit();
    HSTAGE(HBUF, 1);
    cp_commit();

    int buf_id = 0;
    for (int t = 0; t < NT_H; ++t) {
        cp_wait1();
        __syncthreads();
        if (t + 2 < NT_H) {
            int nb = buf_id + 2;
            if (nb >= 3) nb -= 3;
            HSTAGE(nb * HBUF, t + 2);
        }
        cp_commit();
        const uint32_t buf = sbase + buf_id * HBUF;
#pragma unroll
        for (int ks = 0; ks < 4; ++ks) {
            const int col = 2 * ks + khalf;
            uint32_t Ah[2][4];
#pragma unroll
            for (int mf = 0; mf < 2; ++mf) {
                int r = arow[mf];
                ldsm4(buf + r * 128 + ((col ^ (r & 7)) << 4), Ah[mf]);
            }
#pragma unroll
            for (int g = 0; g < 2; ++g) {
                int r = brow[g];
                uint32_t Bv[4];
                ldsm4(buf + HB_OFF + r * 128 + ((col ^ (r & 7)) << 4), Bv);
#pragma unroll
                for (int f = 0; f < 2; ++f)
#pragma unroll
                    for (int mf = 0; mf < 2; ++mf)
                        mma_f16(acc[mf][g * 2 + f], Ah[mf], Bv[f], Bv[f + 2]);
            }
        }
        if (++buf_id == 3) buf_id = 0;
        __syncthreads();
    }

    const int r = lane >> 2;
    const int c2 = (lane & 3) * 2;
    float* hp = g_hp[kb];
#pragma unroll
    for (int mf = 0; mf < 2; ++mf) {
        int row0 = m0 + wm * 32 + mf * 16 + r;
#pragma unroll
        for (int j = 0; j < 4; ++j) {
            int col = wn * 32 + (j >> 1) * 16 + (j & 1) * 8 + c2;
            const float* a4 = acc[mf][j];
            *(float2*)(hp + (size_t)row0 * ERDIM + col) = make_float2(a4[0], a4[1]);
            *(float2*)(hp + (size_t)(row0 + 8) * ERDIM + col) = make_float2(a4[2], a4[3]);
        }
    }
}

// ================= kernel 4: main HMMA (strength-reduced addressing) ====
// CTA 128x128, BK=64 fp16, 8 warps (4m x 2n), warp tile 32x64, 2 CTAs/SM.
#define BM 128
#define BN 128
#define BK 64
#define NT (DDIM / BK)          // 64
#define B_OFF 16384
#define BUFSZ 32768
#define SMEM_BYTES (3 * BUFSZ)  // 98304 -> 2 CTAs/SM

__global__ void __launch_bounds__(256, 2) main_hmma_kernel(
        const float* __restrict__ bias, const float* __restrict__ lB,
        float* __restrict__ out) {
    extern __shared__ __align__(128) char sm[];
    const int tid = threadIdx.x;
    const int lane = tid & 31, wid = tid >> 5;
    const int wm = wid & 3, wn = wid >> 2;
    const uint32_t sbase = cvta_smem(sm);
    const int n0 = blockIdx.x * BN;
    const int m0 = blockIdx.y * BM;
    const int bidx = m0 >> 11;

    const int row16 = ((lane >> 3) & 1) * 8 + (lane & 7);
    const int khalf = lane >> 4;
    int arow[2], brow[4];
#pragma unroll
    for (int f = 0; f < 2; ++f) arow[f] = wm * 32 + f * 16 + row16;
#pragma unroll
    for (int g = 0; g < 4; ++g) brow[g] = wn * 64 + g * 16 + row16;

    // precomputed ldsm base offsets (col = khalf); per ks: addr ^ (ks<<5)
    uint32_t aoff[2], boff[4];
#pragma unroll
    for (int f = 0; f < 2; ++f)
        aoff[f] = arow[f] * 128 + ((khalf ^ (arow[f] & 7)) << 4);
#pragma unroll
    for (int g = 0; g < 4; ++g)
        boff[g] = B_OFF + brow[g] * 128 + ((khalf ^ (brow[g] & 7)) << 4);

    // precomputed staging geometry (thread-constant)
    const int r0 = tid >> 3;            // 0..31
    const int sg = tid & 7;
    const uint32_t dstA0 = r0 * 128 + ((sg ^ (r0 & 7)) << 4);
    const __half* xptr = g_xh + (size_t)(m0 + r0) * DDIM + sg * 8;
    const __half* wptr = g_wh + (size_t)(n0 + r0) * DDIM + sg * 8;

    float acc[2][8][4];
#pragma unroll
    for (int i = 0; i < 2; ++i)
#pragma unroll
        for (int j = 0; j < 8; ++j)
#pragma unroll
            for (int k = 0; k < 4; ++k) acc[i][j][k] = 0.0f;

#define STAGE(bufofs, t)                                                     \
    do {                                                                     \
        const __half* xs_ = xptr + (size_t)(t) * BK;                         \
        const __half* ws_ = wptr + (size_t)(t) * BK;                         \
        const uint32_t da_ = sbase + (bufofs) + dstA0;                       \
        _Pragma("unroll")                                                    \
        for (int i = 0; i < 4; ++i)                                          \
            cp16(da_ + 4096 * i, xs_ + (size_t)i * 32 * DDIM);               \
        _Pragma("unroll")                                                    \
        for (int i = 0; i < 4; ++i)                                          \
            cp16(da_ + B_OFF + 4096 * i, ws_ + (size_t)i * 32 * DDIM);       \
    } while (0)

    STAGE(0, 0);
    cp_commit();
    STAGE(BUFSZ, 1);
    cp_commit();

    int buf_id = 0;
    for (int t = 0; t < NT; ++t) {
        cp_wait1();
        __syncthreads();
        if (t + 2 < NT) {
            int nb = buf_id + 2;
            if (nb >= 3) nb -= 3;
            STAGE(nb * BUFSZ, t + 2);
        }
        cp_commit();
        const uint32_t bufb = sbase + buf_id * BUFSZ;
        uint32_t aab[2], bab[4];
#pragma unroll
        for (int f = 0; f < 2; ++f) aab[f] = bufb + aoff[f];
#pragma unroll
        for (int g = 0; g < 4; ++g) bab[g] = bufb + boff[g];
#pragma unroll
        for (int ks = 0; ks < 4; ++ks) {
            const uint32_t kx = ks << 5;
            uint32_t Ah[2][4];
#pragma unroll
            for (int mf = 0; mf < 2; ++mf) ldsm4(aab[mf] ^ kx, Ah[mf]);
#pragma unroll
            for (int g = 0; g < 4; ++g) {
                uint32_t Bv[4];
                ldsm4(bab[g] ^ kx, Bv);
#pragma unroll
                for (int f = 0; f < 2; ++f)
#pragma unroll
                    for (int mf = 0; mf < 2; ++mf)
                        mma_f16(acc[mf][g * 2 + f], Ah[mf], Bv[f], Bv[f + 2]);
            }
        }
        if (++buf_id == 3) buf_id = 0;
    }

    // ---------------- LoRA chunk (fp16), into buffer 0 ----------------
    cp_wait0();
    __syncthreads();
#pragma unroll
    for (int i = 0; i < 8; ++i) {
        int idx = i * 256 + tid;          // 0..2047
        int row = idx >> 4;               // 0..127 (m row)
        int q = idx & 15;                 // er quad
        int er0 = q * 4;
        float wsc = g_w[bidx * EDIM + (q >> 1)];
        size_t ho = (size_t)(m0 + row) * ERDIM + er0;
        float4 h0 = *(const float4*)(&g_hp[0][ho]);
        float4 h1 = *(const float4*)(&g_hp[1][ho]);
        float4 hv;
        hv.x = (h0.x + h1.x) * wsc;
        hv.y = (h0.y + h1.y) * wsc;
        hv.z = (h0.z + h1.z) * wsc;
        hv.w = (h0.w + h1.w) * wsc;
        int so = row * 128 + (((q >> 1) ^ (row & 7)) << 4) + (q & 1) * 8;
        *(uint2*)(sm + so) = pack_h4(hv);
    }
#pragma unroll
    for (int i = 0; i < 8; ++i) {
        int idx = i * 256 + tid;          // 0..2047
        int row = idx >> 4;               // 0..127 (n row)
        int q = idx & 15;
        int e = q >> 1, r0q = (q & 1) * 4;
        float4 bv = *(const float4*)(lB + (size_t)e * ODIM * RDIM
                                        + (size_t)(n0 + row) * RDIM + r0q);
        int so = B_OFF + row * 128 + (((q >> 1) ^ (row & 7)) << 4) + (q & 1) * 8;
        *(uint2*)(sm + so) = pack_h4(bv);
    }
    __syncthreads();
#pragma unroll
    for (int ks = 0; ks < 4; ++ks) {
        const uint32_t kx = ks << 5;
        uint32_t Ah[2][4];
#pragma unroll
        for (int mf = 0; mf < 2; ++mf) ldsm4((sbase + aoff[mf]) ^ kx, Ah[mf]);
#pragma unroll
        for (int g = 0; g < 4; ++g) {
            uint32_t Bv[4];
            ldsm4((sbase + boff[g]) ^ kx, Bv);
#pragma unroll
            for (int f = 0; f < 2; ++f)
#pragma unroll
                for (int mf = 0; mf < 2; ++mf)
                    mma_f16(acc[mf][g * 2 + f], Ah[mf], Bv[f], Bv[f + 2]);
        }
    }

    // ---------------- writeback with bias ----------------
    const int rr = lane >> 2;
    const int c2 = (lane & 3) * 2;
#pragma unroll
    for (int mf = 0; mf < 2; ++mf) {
        int row0 = m0 + wm * 32 + mf * 16 + rr;
#pragma unroll
        for (int j = 0; j < 8; ++j) {
            int col = n0 + wn * 64 + (j >> 1) * 16 + (j & 1) * 8 + c2;
            float b0 = __ldg(&bias[col]);
            float b1 = __ldg(&bias[col + 1]);
            const float* a4 = acc[mf][j];
            *(float2*)(out + (size_t)row0 * ODIM + col) =
                make_float2(a4[0] + b0, a4[1] + b1);
            *(float2*)(out + (size_t)(row0 + 8) * ODIM + col) =
                make_float2(a4[2] + b0, a4[3] + b1);
        }
    }
}

// ================= launcher =================
extern "C" void kernel_launch(void* const* d_in, const int* in_sizes, int n_in,
                              void* d_out, int out_size) {
    const float* x   = (const float*)d_in[0];   // [B,S,D]
    const float* Wb  = (const float*)d_in[1];   // [O,D]
    const float* bb  = (const float*)d_in[2];   // [O]
    const float* lA  = (const float*)d_in[3];   // [E,R,D]
    const float* lBm = (const float*)d_in[4];   // [E,O,R]
    const float* rW  = (const float*)d_in[5];   // [E,D]
    const float* rb  = (const float*)d_in[6];   // [E]
    float* out = (float*)d_out;                 // [B,S,O]

    cudaFuncSetAttribute(main_hmma_kernel,
                         cudaFuncAttributeMaxDynamicSharedMemorySize, SMEM_BYTES);
    cudaFuncSetAttribute(h_mma_kernel,
                         cudaFuncAttributeMaxDynamicSharedMemorySize, H_SMEM);

    convall_kernel<<<dim3(16, 16, 9), 256>>>(x, Wb, lA);
    router_kernel<<<1, 1024>>>(rW, rb);
    h_mma_kernel<<<dim3(MDIM / 128, 2), 256, H_SMEM>>>();
    main_hmma_kernel<<<dim3(ODIM / BN, MDIM / BM), 256, SMEM_BYTES>>>(bb, lBm, out);
}

// round 14
// speedup vs baseline: 1.0302x; 1.0302x over previous
#include <cuda_runtime.h>
#include <cuda_fp16.h>
#include <stdint.h>
#include <math.h>

#define BDIM   4
#define SDIM   2048
#define DDIM   4096
#define ODIM   4096
#define EDIM   8
#define RDIM   8
#define MDIM   (BDIM*SDIM)     // 8192
#define ERDIM  64
#define SCALING 2.0f

// ---------------- scratch (static device globals; no allocations) -------
__device__ __half g_xh[(size_t)MDIM * DDIM];     // 64 MB  x fp16
__device__ __half g_wh[(size_t)ODIM * DDIM];     // 32 MB  W fp16
__device__ __half g_lah[(size_t)ERDIM * DDIM];   // 512 KB lora_A fp16
__device__ float g_hp[2][MDIM * ERDIM];          // 4 MB   h k-split partials
__device__ float g_xpart[16][BDIM * DDIM];       // 1 MB   colsum partials
__device__ float g_w[BDIM * EDIM];

// ---------------- helpers ----------------
__device__ __forceinline__ uint32_t cvta_smem(const void* p) {
    return (uint32_t)__cvta_generic_to_shared(p);
}
__device__ __forceinline__ void cp16(uint32_t dst, const void* src) {
    asm volatile("cp.async.cg.shared.global [%0], [%1], 16;"
                 :: "r"(dst), "l"(src) : "memory");
}
__device__ __forceinline__ void cp_commit() {
    asm volatile("cp.async.commit_group;" ::: "memory");
}
__device__ __forceinline__ void cp_wait0() {
    asm volatile("cp.async.wait_group 0;" ::: "memory");
}
__device__ __forceinline__ void cp_wait1() {
    asm volatile("cp.async.wait_group 1;" ::: "memory");
}
__device__ __forceinline__ void ldsm4(uint32_t a, uint32_t* r) {
    asm volatile("ldmatrix.sync.aligned.m8n8.x4.shared.b16 {%0,%1,%2,%3}, [%4];"
                 : "=r"(r[0]), "=r"(r[1]), "=r"(r[2]), "=r"(r[3]) : "r"(a));
}
__device__ __forceinline__ void mma_f16(float* d, const uint32_t* a,
                                        uint32_t b0, uint32_t b1) {
    asm volatile(
        "mma.sync.aligned.m16n8k16.row.col.f32.f16.f16.f32 "
        "{%0,%1,%2,%3}, {%4,%5,%6,%7}, {%8,%9}, {%0,%1,%2,%3};"
        : "+f"(d[0]), "+f"(d[1]), "+f"(d[2]), "+f"(d[3])
        : "r"(a[0]), "r"(a[1]), "r"(a[2]), "r"(a[3]), "r"(b0), "r"(b1));
}
__device__ __forceinline__ uint2 pack_h4(float4 v) {
    __half2 a = __floats2half2_rn(v.x, v.y);
    __half2 b = __floats2half2_rn(v.z, v.w);
    uint2 u;
    u.x = *reinterpret_cast<uint32_t*>(&a);
    u.y = *reinterpret_cast<uint32_t*>(&b);
    return u;
}

// ================= kernel 1: fused conversions =================
__global__ void convall_kernel(const float* __restrict__ x,
                               const float* __restrict__ W,
                               const float* __restrict__ lA) {
    if (blockIdx.z < 4) {
        int b = blockIdx.z;
        int d = blockIdx.x * 256 + threadIdx.x;
        int ss = blockIdx.y;
        size_t base = ((size_t)(b * SDIM + ss * 128)) * DDIM + d;
        float acc = 0.0f;
#pragma unroll 4
        for (int s = 0; s < 128; ++s) {
            size_t idx = base + (size_t)s * DDIM;
            float v = x[idx];
            g_xh[idx] = __float2half_rn(v);
            acc += v;
        }
        g_xpart[ss][b * DDIM + d] = acc;
    } else if (blockIdx.z < 8) {
        int zq = blockIdx.z - 4;
        int t = (blockIdx.y * 16 + blockIdx.x) * 256 + threadIdx.x;
#pragma unroll 4
        for (int i = 0; i < 16; ++i) {
            size_t j = (((size_t)zq * 16 + i) * 65536 + t) * 4;
            float4 v = *(const float4*)(W + j);
            *(uint2*)(g_wh + j) = pack_h4(v);
        }
    } else {
        int t = (blockIdx.y * 16 + blockIdx.x) * 256 + threadIdx.x;
        size_t j = (size_t)t * 4;
        float4 v = *(const float4*)(lA + j);
        *(uint2*)(g_lah + j) = pack_h4(v);
    }
}

// ================= kernel 2: h via HMMA + fused router ==================
// blocks (0..63, kb): h partials.  block (64, 0): router softmax.
#define HB_OFF 16384
#define HBUF 24576
#define H_SMEM (3 * HBUF)
#define NT_H 32

__global__ void __launch_bounds__(256, 2) h_mma_kernel(
        const float* __restrict__ rW, const float* __restrict__ rb) {
    extern __shared__ __align__(128) char sm[];
    const int tid = threadIdx.x;
    const int lane = tid & 31, wid = tid >> 5;

    // ---------------- fused router block ----------------
    if (blockIdx.x == 64) {
        if (blockIdx.y != 0) return;
        float* xsum_s = (float*)sm;               // 64 KB in dynamic smem
        __shared__ float logits[BDIM * EDIM];
        // phase A: reduce 16 colsum partials into shared
        for (int i = tid; i < BDIM * DDIM / 4; i += 256) {
            float4 s = make_float4(0.f, 0.f, 0.f, 0.f);
#pragma unroll
            for (int p = 0; p < 16; ++p) {
                float4 v = *(const float4*)(&g_xpart[p][i * 4]);
                s.x += v.x; s.y += v.y; s.z += v.z; s.w += v.w;
            }
            *(float4*)(&xsum_s[i * 4]) = s;
        }
        __syncthreads();
        // phase B: warp w computes 4 (b,e) dot products
#pragma unroll
        for (int q = 0; q < 4; ++q) {
            int be = wid * 4 + q;
            int b = be >> 3, e = be & 7;
            const float* xs = xsum_s + b * DDIM;
            const float* wr = rW + e * DDIM;
            float acc = 0.0f;
            for (int d = lane * 4; d < DDIM; d += 128) {
                float4 xv = *(const float4*)(xs + d);
                float4 wv = *(const float4*)(wr + d);
                acc += xv.x * wv.x + xv.y * wv.y + xv.z * wv.z + xv.w * wv.w;
            }
#pragma unroll
            for (int o = 16; o; o >>= 1)
                acc += __shfl_down_sync(0xffffffffu, acc, o);
            if (lane == 0) logits[be] = acc / (float)SDIM + rb[e];
        }
        __syncthreads();
        if (tid < BDIM) {
            int bb = tid;
            float mx = -1e30f;
#pragma unroll
            for (int ee = 0; ee < EDIM; ++ee)
                mx = fmaxf(mx, logits[bb * EDIM + ee]);
            float sum = 0.0f;
            float ex[EDIM];
#pragma unroll
            for (int ee = 0; ee < EDIM; ++ee) {
                ex[ee] = expf(logits[bb * EDIM + ee] - mx);
                sum += ex[ee];
            }
            float inv = SCALING / sum;
#pragma unroll
            for (int ee = 0; ee < EDIM; ++ee)
                g_w[bb * EDIM + ee] = ex[ee] * inv;
        }
        return;
    }

    // ---------------- h partial blocks ----------------
    const int wm = wid & 3, wn = wid >> 2;
    const uint32_t sbase = cvta_smem(sm);
    const int m0 = blockIdx.x * 128;
    const int kb = blockIdx.y;
    const int kbase = kb * 2048;

    const int row16 = ((lane >> 3) & 1) * 8 + (lane & 7);
    const int khalf = lane >> 4;
    int arow[2], brow[2];
#pragma unroll
    for (int f = 0; f < 2; ++f) {
        arow[f] = wm * 32 + f * 16 + row16;
        brow[f] = wn * 32 + f * 16 + row16;
    }

    float acc[2][4][4];
#pragma unroll
    for (int i = 0; i < 2; ++i)
#pragma unroll
        for (int j = 0; j < 4; ++j)
#pragma unroll
            for (int k = 0; k < 4; ++k) acc[i][j][k] = 0.0f;

#define HSTAGE(bufofs, t)                                                    \
    do {                                                                     \
        _Pragma("unroll")                                                    \
        for (int i = 0; i < 4; ++i) {                                        \
            int idx = i * 256 + tid;                                         \
            int r = idx >> 3, seg = idx & 7;                                 \
            const __half* src = g_xh                                         \
                + (size_t)(m0 + r) * DDIM + kbase + (t) * 64 + seg * 8;      \
            cp16(sbase + (bufofs) + r * 128 + ((seg ^ (r & 7)) << 4), src);  \
        }                                                                    \
        _Pragma("unroll")                                                    \
        for (int i = 0; i < 2; ++i) {                                        \
            int idx = i * 256 + tid;                                         \
            int r = idx >> 3, seg = idx & 7;                                 \
            const __half* src = g_lah                                        \
                + (size_t)r * DDIM + kbase + (t) * 64 + seg * 8;             \
            cp16(sbase + (bufofs) + HB_OFF + r * 128                         \
                 + ((seg ^ (r & 7)) << 4), src);                             \
        }                                                                    \
    } while (0)

    HSTAGE(0, 0);
    cp_commit();
    HSTAGE(HBUF, 1);
    cp_commit();

    int buf_id = 0;
    for (int t = 0; t < NT_H; ++t) {
        cp_wait1();
        __syncthreads();
        if (t + 2 < NT_H) {
            int nb = buf_id + 2;
            if (nb >= 3) nb -= 3;
            HSTAGE(nb * HBUF, t + 2);
        }
        cp_commit();
        const uint32_t buf = sbase + buf_id * HBUF;
#pragma unroll
        for (int ks = 0; ks < 4; ++ks) {
            const int col = 2 * ks + khalf;
            uint32_t Ah[2][4];
#pragma unroll
            for (int mf = 0; mf < 2; ++mf) {
                int r = arow[mf];
                ldsm4(buf + r * 128 + ((col ^ (r & 7)) << 4), Ah[mf]);
            }
#pragma unroll
            for (int g = 0; g < 2; ++g) {
                int r = brow[g];
                uint32_t Bv[4];
                ldsm4(buf + HB_OFF + r * 128 + ((col ^ (r & 7)) << 4), Bv);
#pragma unroll
                for (int f = 0; f < 2; ++f)
#pragma unroll
                    for (int mf = 0; mf < 2; ++mf)
                        mma_f16(acc[mf][g * 2 + f], Ah[mf], Bv[f], Bv[f + 2]);
            }
        }
        if (++buf_id == 3) buf_id = 0;
        __syncthreads();
    }

    const int r = lane >> 2;
    const int c2 = (lane & 3) * 2;
    float* hp = g_hp[kb];
#pragma unroll
    for (int mf = 0; mf < 2; ++mf) {
        int row0 = m0 + wm * 32 + mf * 16 + r;
#pragma unroll
        for (int j = 0; j < 4; ++j) {
            int col = wn * 32 + (j >> 1) * 16 + (j & 1) * 8 + c2;
            const float* a4 = acc[mf][j];
            *(float2*)(hp + (size_t)row0 * ERDIM + col) = make_float2(a4[0], a4[1]);
            *(float2*)(hp + (size_t)(row0 + 8) * ERDIM + col) = make_float2(a4[2], a4[3]);
        }
    }
}

// ================= kernel 3: main HMMA (R12 config — best known) ========
// CTA 128x128, BK=64 fp16, 8 warps (4m x 2n), warp tile 32x64, 2 CTAs/SM.
#define BM 128
#define BN 128
#define BK 64
#define NT (DDIM / BK)          // 64
#define B_OFF 16384
#define BUFSZ 32768
#define SMEM_BYTES (3 * BUFSZ)  // 98304 -> 2 CTAs/SM

__global__ void __launch_bounds__(256, 2) main_hmma_kernel(
        const float* __restrict__ bias, const float* __restrict__ lB,
        float* __restrict__ out) {
    extern __shared__ __align__(128) char sm[];
    const int tid = threadIdx.x;
    const int lane = tid & 31, wid = tid >> 5;
    const int wm = wid & 3, wn = wid >> 2;
    const uint32_t sbase = cvta_smem(sm);
    const int n0 = blockIdx.x * BN;
    const int m0 = blockIdx.y * BM;
    const int bidx = m0 >> 11;

    const int row16 = ((lane >> 3) & 1) * 8 + (lane & 7);
    const int khalf = lane >> 4;
    int arow[2], brow[4];
#pragma unroll
    for (int f = 0; f < 2; ++f) arow[f] = wm * 32 + f * 16 + row16;
#pragma unroll
    for (int g = 0; g < 4; ++g) brow[g] = wn * 64 + g * 16 + row16;

    float acc[2][8][4];
#pragma unroll
    for (int i = 0; i < 2; ++i)
#pragma unroll
        for (int j = 0; j < 8; ++j)
#pragma unroll
            for (int k = 0; k < 4; ++k) acc[i][j][k] = 0.0f;

#define STAGE(bufofs, t)                                                     \
    do {                                                                     \
        _Pragma("unroll")                                                    \
        for (int i = 0; i < 4; ++i) {                                        \
            int idx = i * 256 + tid;                                         \
            int r = idx >> 3, seg = idx & 7;                                 \
            const __half* src = g_xh                                         \
                + (size_t)(m0 + r) * DDIM + (t) * BK + seg * 8;              \
            cp16(sbase + (bufofs) + r * 128 + ((seg ^ (r & 7)) << 4), src);  \
        }                                                                    \
        _Pragma("unroll")                                                    \
        for (int i = 0; i < 4; ++i) {                                        \
            int idx = i * 256 + tid;                                         \
            int r = idx >> 3, seg = idx & 7;                                 \
            const __half* src = g_wh                                         \
                + (size_t)(n0 + r) * DDIM + (t) * BK + seg * 8;              \
            cp16(sbase + (bufofs) + B_OFF + r * 128                          \
                 + ((seg ^ (r & 7)) << 4), src);                             \
        }                                                                    \
    } while (0)

    STAGE(0, 0);
    cp_commit();
    STAGE(BUFSZ, 1);
    cp_commit();

    int buf_id = 0;
    for (int t = 0; t < NT; ++t) {
        cp_wait1();
        __syncthreads();
        if (t + 2 < NT) {
            int nb = buf_id + 2;
            if (nb >= 3) nb -= 3;
            STAGE(nb * BUFSZ, t + 2);
        }
        cp_commit();
        const uint32_t buf = sbase + buf_id * BUFSZ;
#pragma unroll
        for (int ks = 0; ks < 4; ++ks) {
            const int col = 2 * ks + khalf;
            uint32_t Ah[2][4];
#pragma unroll
            for (int mf = 0; mf < 2; ++mf) {
                int r = arow[mf];
                ldsm4(buf + r * 128 + ((col ^ (r & 7)) << 4), Ah[mf]);
            }
#pragma unroll
            for (int g = 0; g < 4; ++g) {
                int r = brow[g];
                uint32_t Bv[4];
                ldsm4(buf + B_OFF + r * 128 + ((col ^ (r & 7)) << 4), Bv);
#pragma unroll
                for (int f = 0; f < 2; ++f)
#pragma unroll
                    for (int mf = 0; mf < 2; ++mf)
                        mma_f16(acc[mf][g * 2 + f], Ah[mf], Bv[f], Bv[f + 2]);
            }
        }
        if (++buf_id == 3) buf_id = 0;
    }

    // ---------------- LoRA chunk (fp16), into buffer 0 ----------------
    cp_wait0();
    __syncthreads();
#pragma unroll
    for (int i = 0; i < 8; ++i) {
        int idx = i * 256 + tid;          // 0..2047
        int row = idx >> 4;               // 0..127 (m row)
        int q = idx & 15;                 // er quad
        int er0 = q * 4;
        float wsc = g_w[bidx * EDIM + (q >> 1)];
        size_t ho = (size_t)(m0 + row) * ERDIM + er0;
        float4 h0 = *(const float4*)(&g_hp[0][ho]);
        float4 h1 = *(const float4*)(&g_hp[1][ho]);
        float4 hv;
        hv.x = (h0.x + h1.x) * wsc;
        hv.y = (h0.y + h1.y) * wsc;
        hv.z = (h0.z + h1.z) * wsc;
        hv.w = (h0.w + h1.w) * wsc;
        int so = row * 128 + (((q >> 1) ^ (row & 7)) << 4) + (q & 1) * 8;
        *(uint2*)(sm + so) = pack_h4(hv);
    }
#pragma unroll
    for (int i = 0; i < 8; ++i) {
        int idx = i * 256 + tid;          // 0..2047
        int row = idx >> 4;               // 0..127 (n row)
        int q = idx & 15;
        int e = q >> 1, r0q = (q & 1) * 4;
        float4 bv = *(const float4*)(lB + (size_t)e * ODIM * RDIM
                                        + (size_t)(n0 + row) * RDIM + r0q);
        int so = B_OFF + row * 128 + (((q >> 1) ^ (row & 7)) << 4) + (q & 1) * 8;
        *(uint2*)(sm + so) = pack_h4(bv);
    }
    __syncthreads();
#pragma unroll
    for (int ks = 0; ks < 4; ++ks) {
        const int col = 2 * ks + khalf;
        uint32_t Ah[2][4];
#pragma unroll
        for (int mf = 0; mf < 2; ++mf) {
            int r = arow[mf];
            ldsm4(sbase + r * 128 + ((col ^ (r & 7)) << 4), Ah[mf]);
        }
#pragma unroll
        for (int g = 0; g < 4; ++g) {
            int r = brow[g];
            uint32_t Bv[4];
            ldsm4(sbase + B_OFF + r * 128 + ((col ^ (r & 7)) << 4), Bv);
#pragma unroll
            for (int f = 0; f < 2; ++f)
#pragma unroll
                for (int mf = 0; mf < 2; ++mf)
                    mma_f16(acc[mf][g * 2 + f], Ah[mf], Bv[f], Bv[f + 2]);
        }
    }

    // ---------------- writeback with bias ----------------
    const int rr = lane >> 2;
    const int c2 = (lane & 3) * 2;
#pragma unroll
    for (int mf = 0; mf < 2; ++mf) {
        int row0 = m0 + wm * 32 + mf * 16 + rr;
#pragma unroll
        for (int j = 0; j < 8; ++j) {
            int col = n0 + wn * 64 + (j >> 1) * 16 + (j & 1) * 8 + c2;
            float b0 = __ldg(&bias[col]);
            float b1 = __ldg(&bias[col + 1]);
            const float* a4 = acc[mf][j];
            *(float2*)(out + (size_t)row0 * ODIM + col) =
                make_float2(a4[0] + b0, a4[1] + b1);
            *(float2*)(out + (size_t)(row0 + 8) * ODIM + col) =
                make_float2(a4[2] + b0, a4[3] + b1);
        }
    }
}

// ================= launcher =================
extern "C" void kernel_launch(void* const* d_in, const int* in_sizes, int n_in,
                              void* d_out, int out_size) {
    const float* x   = (const float*)d_in[0];   // [B,S,D]
    const float* Wb  = (const float*)d_in[1];   // [O,D]
    const float* bb  = (const float*)d_in[2];   // [O]
    const float* lA  = (const float*)d_in[3];   // [E,R,D]
    const float* lBm = (const float*)d_in[4];   // [E,O,R]
    const float* rW  = (const float*)d_in[5];   // [E,D]
    const float* rb  = (const float*)d_in[6];   // [E]
    float* out = (float*)d_out;                 // [B,S,O]

    cudaFuncSetAttribute(main_hmma_kernel,
                         cudaFuncAttributeMaxDynamicSharedMemorySize, SMEM_BYTES);
    cudaFuncSetAttribute(h_mma_kernel,
                         cudaFuncAttributeMaxDynamicSharedMemorySize, H_SMEM);

    convall_kernel<<<dim3(16, 16, 9), 256>>>(x, Wb, lA);
    h_mma_kernel<<<dim3(65, 2), 256, H_SMEM>>>(rW, rb);
    main_hmma_kernel<<<dim3(ODIM / BN, MDIM / BM), 256, SMEM_BYTES>>>(bb, lBm, out);
}